// round 15
// baseline (speedup 1.0000x reference)
#include <cuda_runtime.h>

// Shapes fixed per reference: N=100000, E=1200000, B=100000, IDIM=128, H1=H2=64.
#define NMAX 100000
#define EMAX 1200000
#define BMAX 100000

// gemm1 dynamic smem: xraw[2][128][36] + wf[2][1024] float4 (both double-buffered)
#define G1_XRAW_BYTES (2 * 128 * 36 * 4)   // 36864
#define G1_WF_BYTES   (2 * 1024 * 16)      // 32768
#define G1_SMEM       (G1_XRAW_BYTES + G1_WF_BYTES)  // 69632

__device__ float g_deg_in [NMAX];     // rsqrt(max(in_deg,1))
__device__ float g_deg_out[NMAX];     // rsqrt(max(out_deg,1))
__device__ int   g_cnt_out[NMAX];
__device__ int   g_cnt_in [NMAX];
__device__ int   g_offs   [NMAX];     // CSR row starts (by dst)
__device__ int   g_cur    [NMAX];     // fill cursors; == row end after fill
__device__ int   g_bsum   [128];      // scan1 raw block sums
__device__ int   g_csr    [EMAX];     // src ids grouped by dst
__device__ float g_h  [NMAX * 64];    // pre-aggregation features
__device__ float g_v  [NMAX * 64];    // node features v1 / v2
__device__ float g_emb[BMAX * 64];    // fc1 output (pre-BN2)
__device__ float g_stats[256];        // [0:64) sum1 [64:128) sq1 [128:192) sum2 [192:256) sq2

// Precomputed tf32 hi/lo B-fragment tables (built once per replay by k_prep0).
__device__ float4 g_wf1 [4096];   // W1  (K=128)
__device__ float4 g_wf2 [2048];   // W2  (K=64)
__device__ float4 g_wff1[2048];   // fc1_w
__device__ float4 g_wff2[2048];   // fc2_w

__device__ __forceinline__ float lrelu(float v) { return v > 0.0f ? v : 0.01f * v; }

// cp.async helpers (16B, cache-global; src_sz=0 -> zero-fill dst)
__device__ __forceinline__ void cp16(void* dst_smem, const void* src_gmem, int src_sz) {
    unsigned ds = (unsigned)__cvta_generic_to_shared(dst_smem);
    asm volatile("cp.async.cg.shared.global [%0], [%1], 16, %2;\n"
                 :: "r"(ds), "l"(src_gmem), "r"(src_sz));
}
#define CP_COMMIT() asm volatile("cp.async.commit_group;\n" ::: "memory")
#define CP_WAIT1()  asm volatile("cp.async.wait_group 1;\n" ::: "memory")
#define CP_WAIT0()  asm volatile("cp.async.wait_group 0;\n" ::: "memory")

// tf32 helpers: hi = round-to-nearest tf32; lo = v - hi (3xTF32 split).
__device__ __forceinline__ unsigned f2tf32(float f) {
    unsigned u; asm("cvt.rna.tf32.f32 %0, %1;" : "=r"(u) : "f"(f)); return u;
}
__device__ __forceinline__ void tf32_split(float v, unsigned& hi, unsigned& lo) {
    hi = f2tf32(v);
    lo = f2tf32(v - __uint_as_float(hi));
}

// D(m16n8, fp32) += A(m16k8, tf32) * B(k8n8, tf32)
#define MMA_TF32(d, a0, a1, a2, a3, b0, b1) \
    asm("mma.sync.aligned.m16n8k8.row.col.f32.tf32.tf32.f32 " \
        "{%0,%1,%2,%3},{%4,%5,%6,%7},{%8,%9},{%0,%1,%2,%3};" \
        : "+f"((d)[0]), "+f"((d)[1]), "+f"((d)[2]), "+f"((d)[3]) \
        : "r"(a0), "r"(a1), "r"(a2), "r"(a3), "r"(b0), "r"(b1))

// MMA mainloop over K=64 with 3xTF32 reading a precomputed L2 fragment table.
#define MMA_LOOP64T(acc, xs, wt)                                             \
    _Pragma("unroll")                                                        \
    for (int ks = 0; ks < 8; ks++) {                                         \
        int kk = ks * 8;                                                     \
        float a0 = xs[wr + gid    ][kk + tig    ];                           \
        float a1 = xs[wr + gid + 8][kk + tig    ];                           \
        float a2 = xs[wr + gid    ][kk + tig + 4];                           \
        float a3 = xs[wr + gid + 8][kk + tig + 4];                           \
        unsigned ah0, al0, ah1, al1, ah2, al2, ah3, al3;                     \
        tf32_split(a0, ah0, al0);                                            \
        tf32_split(a1, ah1, al1);                                            \
        tf32_split(a2, ah2, al2);                                            \
        tf32_split(a3, ah3, al3);                                            \
        _Pragma("unroll")                                                    \
        for (int nt = 0; nt < 8; nt++) {                                     \
            float4 wf = __ldg(&(wt)[(ks * 8 + nt) * 32 + lane]);             \
            unsigned bh0 = __float_as_uint(wf.x), bh1 = __float_as_uint(wf.y); \
            unsigned bl0 = __float_as_uint(wf.z), bl1 = __float_as_uint(wf.w); \
            MMA_TF32(acc[nt], ah0, ah1, ah2, ah3, bh0, bh1);                 \
            MMA_TF32(acc[nt], ah0, ah1, ah2, ah3, bl0, bl1);                 \
            MMA_TF32(acc[nt], al0, al1, al2, al3, bh0, bh1);                 \
        }                                                                    \
    }

// ---------------------------------------------------------------------------
// prep0: fragment precompute (first 10240 threads) + counter/stat zeroing.
// ---------------------------------------------------------------------------
__global__ void k_prep0(const float* __restrict__ W1, const float* __restrict__ W2,
                        const float* __restrict__ Wf1, const float* __restrict__ Wf2,
                        int n) {
    int i = blockIdx.x * blockDim.x + threadIdx.x;
    if (i < 10240) {
        const float* W; float4* dst; int e;
        if (i < 4096)      { W = W1;  dst = g_wf1;  e = i; }
        else if (i < 6144) { W = W2;  dst = g_wf2;  e = i - 4096; }
        else if (i < 8192) { W = Wf1; dst = g_wff1; e = i - 6144; }
        else               { W = Wf2; dst = g_wff2; e = i - 8192; }
        int ks = e >> 8, nt = (e >> 5) & 7, ln = e & 31;
        int k0 = ks * 8 + (ln & 3);
        int nn = (ln >> 2) + 8 * nt;
        float w0 = W[k0 * 64 + nn];
        float w1 = W[(k0 + 4) * 64 + nn];
        unsigned h0, l0, h1, l1;
        tf32_split(w0, h0, l0);
        tf32_split(w1, h1, l1);
        dst[e] = make_float4(__uint_as_float(h0), __uint_as_float(h1),
                             __uint_as_float(l0), __uint_as_float(l1));
    }
    int st = gridDim.x * blockDim.x;
    for (int j = i; j < n; j += st) { g_cnt_out[j] = 0; g_cnt_in[j] = 0; }
    if (i < 256) g_stats[i] = 0.0f;
}

__global__ void k_deg(const int* __restrict__ src, const int* __restrict__ dst, int E) {
    int e = blockIdx.x * blockDim.x + threadIdx.x;
    if (e < E) {
        atomicAdd(&g_cnt_out[src[e]], 1);
        atomicAdd(&g_cnt_in [dst[e]], 1);
    }
}

__global__ void k_scan1(int n) {
    __shared__ int sh[256];
    int t = threadIdx.x, b = blockIdx.x;
    int base = b * 1024 + t * 4;
    int v0 = (base + 0 < n) ? g_cnt_in[base + 0] : 0;
    int v1 = (base + 1 < n) ? g_cnt_in[base + 1] : 0;
    int v2 = (base + 2 < n) ? g_cnt_in[base + 2] : 0;
    int v3 = (base + 3 < n) ? g_cnt_in[base + 3] : 0;
    int tsum = v0 + v1 + v2 + v3;
    sh[t] = tsum;
    __syncthreads();
    for (int o = 1; o < 256; o <<= 1) {
        int x = (t >= o) ? sh[t - o] : 0;
        __syncthreads();
        sh[t] += x;
        __syncthreads();
    }
    int excl = sh[t] - tsum;
    if (base + 0 < n) g_offs[base + 0] = excl;
    if (base + 1 < n) g_offs[base + 1] = excl + v0;
    if (base + 2 < n) g_offs[base + 2] = excl + v0 + v1;
    if (base + 3 < n) g_offs[base + 3] = excl + v0 + v1 + v2;
    if (t == 255) g_bsum[b] = sh[255];
}

__global__ void k_scan3(int n, int nblk) {
    __shared__ int bs[128];
    int t = threadIdx.x;
    if (t < 128) {
        int v = (t < nblk) ? g_bsum[t] : 0;
        bs[t] = v;
    }
    __syncthreads();
    #pragma unroll
    for (int o = 1; o < 128; o <<= 1) {
        int x = 0;
        if (t < 128 && t >= o) x = bs[t - o];
        __syncthreads();
        if (t < 128) bs[t] += x;
        __syncthreads();
    }
    int i = blockIdx.x * blockDim.x + t;
    if (i < n) {
        int chunk = i >> 10;
        int coff = (chunk == 0) ? 0 : bs[chunk - 1];
        int off = g_offs[i] + coff;
        g_offs[i] = off;
        g_cur[i]  = off;
        g_deg_in [i] = rsqrtf(fmaxf((float)g_cnt_in [i], 1.0f));
        g_deg_out[i] = rsqrtf(fmaxf((float)g_cnt_out[i], 1.0f));
    }
}

__global__ void k_fill(const int* __restrict__ src, const int* __restrict__ dst, int E) {
    int e = blockIdx.x * blockDim.x + threadIdx.x;
    if (e < E) {
        int d = dst[e];
        int p = atomicAdd(&g_cur[d], 1);
        g_csr[p] = src[e];
    }
}

// ---------------------------------------------------------------------------
// GEMM1 (tensor cores, K=128, frozen from R13/R14): 37.5us, tensor=48%.
// ---------------------------------------------------------------------------
__global__ __launch_bounds__(256, 3) void k_gemm1(const float* __restrict__ x, int n) {
    extern __shared__ __align__(16) char g1s[];
    float (*xraw)[128][36] = (float (*)[128][36])g1s;                 // [2][128][36]
    float4 (*wf)[1024]     = (float4 (*)[1024])(g1s + G1_XRAW_BYTES); // [2][1024]

    int t = threadIdx.x;
    int w = t >> 5, lane = t & 31;
    int gid = lane >> 2, tig = lane & 3;
    int row0 = blockIdx.x * 128;
    int wr = w * 16;

    auto load_chunk = [&](int c, int s) {
        int kc = c * 32;
        #pragma unroll
        for (int ii = 0; ii < 4; ii++) {
            int i = t + ii * 256;
            int r = i >> 3, c16 = (i & 7) * 4;
            int gr = row0 + r;
            cp16(&xraw[s][r][c16], &x[(long)gr * 128 + kc + c16], (gr < n) ? 16 : 0);
        }
        #pragma unroll
        for (int ii = 0; ii < 4; ii++) {
            int e = t + ii * 256;
            cp16(&wf[s][e], &g_wf1[c * 1024 + e], 16);
        }
        CP_COMMIT();
    };

    float acc[8][4];
    #pragma unroll
    for (int nt = 0; nt < 8; nt++)
        #pragma unroll
        for (int j = 0; j < 4; j++) acc[nt][j] = 0.0f;

    load_chunk(0, 0);
    for (int c = 0; c < 4; c++) {
        int s = c & 1;
        __syncthreads();
        if (c < 3) { load_chunk(c + 1, s ^ 1); CP_WAIT1(); }
        else       { CP_WAIT0(); }
        __syncthreads();
        #pragma unroll
        for (int ks = 0; ks < 4; ks++) {
            int kk = ks * 8;
            float a0 = xraw[s][wr + gid    ][kk + tig    ];
            float a1 = xraw[s][wr + gid + 8][kk + tig    ];
            float a2 = xraw[s][wr + gid    ][kk + tig + 4];
            float a3 = xraw[s][wr + gid + 8][kk + tig + 4];
            unsigned ah0, al0, ah1, al1, ah2, al2, ah3, al3;
            tf32_split(a0, ah0, al0);
            tf32_split(a1, ah1, al1);
            tf32_split(a2, ah2, al2);
            tf32_split(a3, ah3, al3);
            #pragma unroll
            for (int nt = 0; nt < 8; nt++) {
                float4 f = wf[s][(ks * 8 + nt) * 32 + lane];
                unsigned bh0 = __float_as_uint(f.x), bh1 = __float_as_uint(f.y);
                unsigned bl0 = __float_as_uint(f.z), bl1 = __float_as_uint(f.w);
                MMA_TF32(acc[nt], ah0, ah1, ah2, ah3, bh0, bh1);
                MMA_TF32(acc[nt], ah0, ah1, ah2, ah3, bl0, bl1);
                MMA_TF32(acc[nt], al0, al1, al2, al3, bh0, bh1);
            }
        }
    }
    int r_lo = row0 + wr + gid;
    int r_hi = r_lo + 8;
    float s_lo = (r_lo < n) ? rsqrtf(fmaxf((float)g_cnt_out[r_lo], 1.0f)) : 0.0f;
    float s_hi = (r_hi < n) ? rsqrtf(fmaxf((float)g_cnt_out[r_hi], 1.0f)) : 0.0f;
    #pragma unroll
    for (int nt = 0; nt < 8; nt++) {
        int cc = nt * 8 + tig * 2;
        if (r_lo < n)
            *(float2*)&g_h[r_lo * 64 + cc] = make_float2(acc[nt][0] * s_lo, acc[nt][1] * s_lo);
        if (r_hi < n)
            *(float2*)&g_h[r_hi * 64 + cc] = make_float2(acc[nt][2] * s_hi, acc[nt][3] * s_hi);
    }
}

// ---------------------------------------------------------------------------
// Aggregate 1 (CSR): g_v[d] = sum g_h[src]*deg_in + b1, plus BN1 stats.
// Half-warp per row: 16 lanes x float4 (full 256B row per gather), 2 rows
// in flight per warp -> 2x memory-level parallelism vs 1 row/warp.
// ---------------------------------------------------------------------------
__global__ void k_agg1(const float* __restrict__ b1, int n) {
    __shared__ float ss[64], sq[64];
    int t = threadIdx.x;
    if (t < 64) { ss[t] = 0.0f; sq[t] = 0.0f; }
    __syncthreads();
    int hl = t & 15;                       // lane in half-warp
    int ghw = (blockIdx.x * blockDim.x + t) >> 4;   // global half-warp id
    int nhw = (gridDim.x * blockDim.x) >> 4;
    int c0 = hl * 4;
    float4 bb = *(const float4*)&b1[c0];
    float s[4] = {0, 0, 0, 0}, q[4] = {0, 0, 0, 0};
    for (int row = ghw; row < n; row += nhw) {
        int e = g_offs[row], end = g_cur[row];
        float a0 = 0, a1 = 0, a2 = 0, a3 = 0;
        float u0 = 0, u1 = 0, u2 = 0, u3 = 0;
        for (; e + 4 <= end; e += 4) {
            int sA = __ldg(&g_csr[e + 0]);
            int sB = __ldg(&g_csr[e + 1]);
            int sC = __ldg(&g_csr[e + 2]);
            int sD = __ldg(&g_csr[e + 3]);
            float4 vA = *(const float4*)&g_h[sA * 64 + c0];
            float4 vB = *(const float4*)&g_h[sB * 64 + c0];
            float4 vC = *(const float4*)&g_h[sC * 64 + c0];
            float4 vD = *(const float4*)&g_h[sD * 64 + c0];
            a0 += vA.x + vC.x; a1 += vA.y + vC.y; a2 += vA.z + vC.z; a3 += vA.w + vC.w;
            u0 += vB.x + vD.x; u1 += vB.y + vD.y; u2 += vB.z + vD.z; u3 += vB.w + vD.w;
        }
        for (; e < end; e++) {
            int sE = __ldg(&g_csr[e]);
            float4 v = *(const float4*)&g_h[sE * 64 + c0];
            a0 += v.x; a1 += v.y; a2 += v.z; a3 += v.w;
        }
        a0 += u0; a1 += u1; a2 += u2; a3 += u3;
        float sc = g_deg_in[row];
        a0 = fmaf(a0, sc, bb.x);
        a1 = fmaf(a1, sc, bb.y);
        a2 = fmaf(a2, sc, bb.z);
        a3 = fmaf(a3, sc, bb.w);
        *(float4*)&g_v[row * 64 + c0] = make_float4(a0, a1, a2, a3);
        s[0] += a0; q[0] += a0 * a0;
        s[1] += a1; q[1] += a1 * a1;
        s[2] += a2; q[2] += a2 * a2;
        s[3] += a3; q[3] += a3 * a3;
    }
    #pragma unroll
    for (int j = 0; j < 4; j++) {
        atomicAdd(&ss[c0 + j], s[j]);
        atomicAdd(&sq[c0 + j], q[j]);
    }
    __syncthreads();
    if (t < 64) { atomicAdd(&g_stats[t], ss[t]); atomicAdd(&g_stats[64 + t], sq[t]); }
}

// ---------------------------------------------------------------------------
// GEMM2 (tensor cores, K=64): g_h = (leaky(bn1(g_v)) * deg_out_scale) @ W2
// ---------------------------------------------------------------------------
__global__ __launch_bounds__(256, 3) void k_gemm2f(const float* __restrict__ bn1g,
        const float* __restrict__ bn1b, int n, float invn) {
    __shared__ __align__(16) float xs[128][68];
    __shared__ float ds[128];
    __shared__ float bnS[64], bnB[64];

    int t = threadIdx.x;
    int w = t >> 5, lane = t & 31;
    int gid = lane >> 2, tig = lane & 3;
    int row0 = blockIdx.x * 128;
    int wr = w * 16;

    if (t < 128) { int gr = row0 + t; ds[t] = (gr < n) ? g_deg_out[gr] : 0.0f; }
    if (t >= 128 && t < 192) {
        int c = t - 128;
        float mu  = g_stats[c] * invn;
        float var = g_stats[64 + c] * invn - mu * mu;
        float s = rsqrtf(var + 1e-5f) * bn1g[c];
        bnS[c] = s;
        bnB[c] = bn1b[c] - mu * s;
    }
    __syncthreads();

    #pragma unroll
    for (int ii = 0; ii < 32; ii++) {
        int i = t + ii * 256;
        int r = i >> 6, k = i & 63;
        int gr = row0 + r;
        float v = 0.0f;
        if (gr < n) v = lrelu(fmaf(g_v[gr * 64 + k], bnS[k], bnB[k])) * ds[r];
        xs[r][k] = v;
    }
    __syncthreads();

    float acc[8][4];
    #pragma unroll
    for (int nt = 0; nt < 8; nt++)
        #pragma unroll
        for (int j = 0; j < 4; j++) acc[nt][j] = 0.0f;
    MMA_LOOP64T(acc, xs, g_wf2);

    int r_lo = row0 + wr + gid;
    int r_hi = r_lo + 8;
    #pragma unroll
    for (int nt = 0; nt < 8; nt++) {
        int cc = nt * 8 + tig * 2;
        if (r_lo < n) *(float2*)&g_h[r_lo * 64 + cc] = make_float2(acc[nt][0], acc[nt][1]);
        if (r_hi < n) *(float2*)&g_h[r_hi * 64 + cc] = make_float2(acc[nt][2], acc[nt][3]);
    }
}

// ---------------------------------------------------------------------------
// Aggregate 2 (CSR): g_v[d] = relu(sum g_h[src]*deg_in + b2). Half-warp rows.
// ---------------------------------------------------------------------------
__global__ void k_agg2(const float* __restrict__ b2, int n) {
    int t = threadIdx.x;
    int hl = t & 15;
    int ghw = (blockIdx.x * blockDim.x + t) >> 4;
    int nhw = (gridDim.x * blockDim.x) >> 4;
    int c0 = hl * 4;
    float4 bb = *(const float4*)&b2[c0];
    for (int row = ghw; row < n; row += nhw) {
        int e = g_offs[row], end = g_cur[row];
        float a0 = 0, a1 = 0, a2 = 0, a3 = 0;
        float u0 = 0, u1 = 0, u2 = 0, u3 = 0;
        for (; e + 4 <= end; e += 4) {
            int sA = __ldg(&g_csr[e + 0]);
            int sB = __ldg(&g_csr[e + 1]);
            int sC = __ldg(&g_csr[e + 2]);
            int sD = __ldg(&g_csr[e + 3]);
            float4 vA = *(const float4*)&g_h[sA * 64 + c0];
            float4 vB = *(const float4*)&g_h[sB * 64 + c0];
            float4 vC = *(const float4*)&g_h[sC * 64 + c0];
            float4 vD = *(const float4*)&g_h[sD * 64 + c0];
            a0 += vA.x + vC.x; a1 += vA.y + vC.y; a2 += vA.z + vC.z; a3 += vA.w + vC.w;
            u0 += vB.x + vD.x; u1 += vB.y + vD.y; u2 += vB.z + vD.z; u3 += vB.w + vD.w;
        }
        for (; e < end; e++) {
            int sE = __ldg(&g_csr[e]);
            float4 v = *(const float4*)&g_h[sE * 64 + c0];
            a0 += v.x; a1 += v.y; a2 += v.z; a3 += v.w;
        }
        a0 += u0; a1 += u1; a2 += u2; a3 += u3;
        float sc = g_deg_in[row];
        a0 = fmaxf(fmaf(a0, sc, bb.x), 0.0f);
        a1 = fmaxf(fmaf(a1, sc, bb.y), 0.0f);
        a2 = fmaxf(fmaf(a2, sc, bb.z), 0.0f);
        a3 = fmaxf(fmaf(a3, sc, bb.w), 0.0f);
        *(float4*)&g_v[row * 64 + c0] = make_float4(a0, a1, a2, a3);
    }
}

// ---------------------------------------------------------------------------
// fc1 (tensor cores, K=64): emb = v[i0]-v[i1]; g_emb = emb @ fc1_w + b; BN2 stats.
// ---------------------------------------------------------------------------
__global__ __launch_bounds__(256, 3) void k_fc1(const int* __restrict__ bidx,
        const float* __restrict__ bias, int Bn) {
    __shared__ __align__(16) float xs[128][68];
    __shared__ int i0s[128], i1s[128];
    __shared__ float ss[64], sq[64], biass[64];

    int t = threadIdx.x;
    int w = t >> 5, lane = t & 31;
    int gid = lane >> 2, tig = lane & 3;
    int row0 = blockIdx.x * 128;
    int wr = w * 16;

    if (t < 128) {
        int gr = row0 + t;
        i0s[t] = (gr < Bn) ? bidx[gr] : 0;
        i1s[t] = (gr < Bn) ? bidx[Bn + gr] : 0;
    }
    if (t >= 128 && t < 192) {
        int c = t - 128;
        ss[c] = 0.0f; sq[c] = 0.0f; biass[c] = bias[c];
    }
    __syncthreads();

    #pragma unroll
    for (int ii = 0; ii < 32; ii++) {
        int i = t + ii * 256;
        int r = i >> 6, k = i & 63;
        float v = 0.0f;
        if (row0 + r < Bn) v = g_v[i0s[r] * 64 + k] - g_v[i1s[r] * 64 + k];
        xs[r][k] = v;
    }
    __syncthreads();

    float acc[8][4];
    #pragma unroll
    for (int nt = 0; nt < 8; nt++)
        #pragma unroll
        for (int j = 0; j < 4; j++) acc[nt][j] = 0.0f;
    MMA_LOOP64T(acc, xs, g_wff1);

    int r_lo = row0 + wr + gid;
    int r_hi = r_lo + 8;
    bool ok_lo = r_lo < Bn, ok_hi = r_hi < Bn;
    #pragma unroll
    for (int nt = 0; nt < 8; nt++) {
        int cc = nt * 8 + tig * 2;
        float b0 = biass[cc], b1 = biass[cc + 1];
        float sa0 = 0.0f, qa0 = 0.0f, sa1 = 0.0f, qa1 = 0.0f;
        if (ok_lo) {
            float a0 = acc[nt][0] + b0, a1 = acc[nt][1] + b1;
            *(float2*)&g_emb[r_lo * 64 + cc] = make_float2(a0, a1);
            sa0 += a0; qa0 += a0 * a0; sa1 += a1; qa1 += a1 * a1;
        }
        if (ok_hi) {
            float a2 = acc[nt][2] + b0, a3 = acc[nt][3] + b1;
            *(float2*)&g_emb[r_hi * 64 + cc] = make_float2(a2, a3);
            sa0 += a2; qa0 += a2 * a2; sa1 += a3; qa1 += a3 * a3;
        }
        atomicAdd(&ss[cc], sa0);     atomicAdd(&sq[cc], qa0);
        atomicAdd(&ss[cc + 1], sa1); atomicAdd(&sq[cc + 1], qa1);
    }
    __syncthreads();
    if (t < 64) {
        atomicAdd(&g_stats[128 + t], ss[t]);
        atomicAdd(&g_stats[192 + t], sq[t]);
    }
}

// ---------------------------------------------------------------------------
// Final (tensor cores, K=64): y = leaky(bn2(g_emb)); z = leaky(y @ fc2_w + b2f);
// out = z @ fc3_w + b3. Quad-shuffle reduction for the fc3 dot.
// ---------------------------------------------------------------------------
__global__ __launch_bounds__(256, 3) void k_final(const float* __restrict__ b2f,
        const float* __restrict__ w3, const float* __restrict__ b3,
        const float* __restrict__ g2, const float* __restrict__ bb2,
        int Bn, float invB, float* __restrict__ out) {
    __shared__ __align__(16) float xs[128][68];
    __shared__ float bnS[64], bnB[64], w3s[64], b2fs[64];

    int t = threadIdx.x;
    int w = t >> 5, lane = t & 31;
    int gid = lane >> 2, tig = lane & 3;
    int row0 = blockIdx.x * 128;
    int wr = w * 16;

    if (t < 64) {
        float mu  = g_stats[128 + t] * invB;
        float var = g_stats[192 + t] * invB - mu * mu;
        float s = rsqrtf(var + 1e-5f) * g2[t];
        bnS[t] = s;
        bnB[t] = bb2[t] - mu * s;
        w3s[t] = w3[t];
        b2fs[t] = b2f[t];
    }
    __syncthreads();

    #pragma unroll
    for (int ii = 0; ii < 32; ii++) {
        int i = t + ii * 256;
        int r = i >> 6, k = i & 63;
        int gr = row0 + r;
        float v = 0.0f;
        if (gr < Bn) v = lrelu(fmaf(g_emb[gr * 64 + k], bnS[k], bnB[k]));
        xs[r][k] = v;
    }
    __syncthreads();

    float acc[8][4];
    #pragma unroll
    for (int nt = 0; nt < 8; nt++)
        #pragma unroll
        for (int j = 0; j < 4; j++) acc[nt][j] = 0.0f;
    MMA_LOOP64T(acc, xs, g_wff2);

    float p_lo = 0.0f, p_hi = 0.0f;
    #pragma unroll
    for (int nt = 0; nt < 8; nt++) {
        int cc = nt * 8 + tig * 2;
        float b0 = b2fs[cc], b1 = b2fs[cc + 1];
        float w0 = w3s[cc],  w1 = w3s[cc + 1];
        p_lo = fmaf(lrelu(acc[nt][0] + b0), w0, p_lo);
        p_lo = fmaf(lrelu(acc[nt][1] + b1), w1, p_lo);
        p_hi = fmaf(lrelu(acc[nt][2] + b0), w0, p_hi);
        p_hi = fmaf(lrelu(acc[nt][3] + b1), w1, p_hi);
    }
    #pragma unroll
    for (int o = 1; o < 4; o <<= 1) {
        p_lo += __shfl_xor_sync(0xffffffffu, p_lo, o);
        p_hi += __shfl_xor_sync(0xffffffffu, p_hi, o);
    }
    int r_lo = row0 + wr + gid;
    int r_hi = r_lo + 8;
    if (tig == 0) {
        float bb = b3[0];
        if (r_lo < Bn) out[r_lo] = p_lo + bb;
        if (r_hi < Bn) out[r_hi] = p_hi + bb;
    }
}

// ---------------------------------------------------------------------------
extern "C" void kernel_launch(void* const* d_in, const int* in_sizes, int n_in,
                              void* d_out, int out_size) {
    const float* x    = (const float*)d_in[0];
    const int*   src  = (const int*)  d_in[1];
    const int*   dst  = (const int*)  d_in[2];
    const int*   bidx = (const int*)  d_in[3];
    const float* W1   = (const float*)d_in[4];
    const float* b1   = (const float*)d_in[5];
    const float* W2   = (const float*)d_in[6];
    const float* b2   = (const float*)d_in[7];
    const float* fc1w = (const float*)d_in[8];
    const float* fc1b = (const float*)d_in[9];
    const float* fc2w = (const float*)d_in[10];
    const float* fc2b = (const float*)d_in[11];
    const float* fc3w = (const float*)d_in[12];
    const float* fc3b = (const float*)d_in[13];
    const float* bn1g = (const float*)d_in[14];
    const float* bn1b = (const float*)d_in[15];
    const float* bn2g = (const float*)d_in[16];
    const float* bn2b = (const float*)d_in[17];

    int n  = in_sizes[0] / 128;   // nodes
    int E  = in_sizes[1];         // edges
    int Bn = in_sizes[3] / 2;     // pairs
    float* out = (float*)d_out;

    int eb  = (E + 255) / 256;
    int nb  = (n + 255) / 256;
    int nsb = (n + 1023) / 1024;
    int gb  = (n + 127) / 128;
    int gbB = (Bn + 127) / 128;

    static bool attr_done = false;
    if (!attr_done) {
        cudaFuncSetAttribute(k_gemm1, cudaFuncAttributeMaxDynamicSharedMemorySize, G1_SMEM);
        attr_done = true;
    }

    // 11 launches; gemm1 at slot 4 (profiled)
    k_prep0<<<512, 256>>>(W1, W2, fc1w, fc2w, n);
    k_deg  <<<eb, 256>>>(src, dst, E);
    k_scan1<<<nsb, 256>>>(n);
    k_gemm1<<<gb, 256, G1_SMEM>>>(x, n);
    k_scan3<<<nb, 256>>>(n, nsb);
    k_fill <<<eb, 256>>>(src, dst, E);

    // conv1 aggregation
    k_agg1 <<<1184, 256>>>(b1, n);

    // conv2 (bn1 + leaky fused into gemm2 load)
    k_gemm2f<<<gb, 256>>>(bn1g, bn1b, n, 1.0f / n);
    k_agg2  <<<1184, 256>>>(b2, n);

    // head
    k_fc1  <<<gbB, 256>>>(bidx, fc1b, Bn);
    k_final<<<gbB, 256>>>(fc2b, fc3w, fc3b, bn2g, bn2b, Bn, 1.0f / Bn, out);
}

// round 16
// speedup vs baseline: 1.0536x; 1.0536x over previous
#include <cuda_runtime.h>

// Shapes fixed per reference: N=100000, E=1200000, B=100000, IDIM=128, H1=H2=64.
#define NMAX 100000
#define EMAX 1200000
#define BMAX 100000

// gemm1 dynamic smem: xraw[2][128][36] + wf[2][1024] float4 (both double-buffered)
#define G1_XRAW_BYTES (2 * 128 * 36 * 4)   // 36864
#define G1_WF_BYTES   (2 * 1024 * 16)      // 32768
#define G1_SMEM       (G1_XRAW_BYTES + G1_WF_BYTES)  // 69632

__device__ float g_deg_in [NMAX];     // rsqrt(max(in_deg,1))
__device__ float g_deg_out[NMAX];     // rsqrt(max(out_deg,1))
__device__ int   g_cnt_out[NMAX];
__device__ int   g_cnt_in [NMAX];
__device__ int   g_offs   [NMAX];     // CSR row starts (by dst)
__device__ int   g_cur    [NMAX];     // fill cursors; == row end after fill
__device__ int   g_bsum   [128];      // scan1 raw block sums
__device__ int   g_csr    [EMAX];     // src ids grouped by dst
__device__ float g_h  [NMAX * 64];    // pre-aggregation features
__device__ float g_v  [NMAX * 64];    // node features v1 / v2
__device__ float g_emb[BMAX * 64];    // fc1 output (pre-BN2)
__device__ float g_stats[256];        // [0:64) sum1 [64:128) sq1 [128:192) sum2 [192:256) sq2

// Precomputed tf32 hi/lo B-fragment tables (built once per replay by k_prep0).
__device__ float4 g_wf1 [4096];   // W1  (K=128)
__device__ float4 g_wf2 [2048];   // W2  (K=64)
__device__ float4 g_wff1[2048];   // fc1_w
__device__ float4 g_wff2[2048];   // fc2_w

__device__ __forceinline__ float lrelu(float v) { return v > 0.0f ? v : 0.01f * v; }

// cp.async helpers (16B, cache-global; src_sz=0 -> zero-fill dst)
__device__ __forceinline__ void cp16(void* dst_smem, const void* src_gmem, int src_sz) {
    unsigned ds = (unsigned)__cvta_generic_to_shared(dst_smem);
    asm volatile("cp.async.cg.shared.global [%0], [%1], 16, %2;\n"
                 :: "r"(ds), "l"(src_gmem), "r"(src_sz));
}
#define CP_COMMIT() asm volatile("cp.async.commit_group;\n" ::: "memory")
#define CP_WAIT1()  asm volatile("cp.async.wait_group 1;\n" ::: "memory")
#define CP_WAIT0()  asm volatile("cp.async.wait_group 0;\n" ::: "memory")

// tf32 helpers: hi = round-to-nearest tf32; lo = v - hi (3xTF32 split).
__device__ __forceinline__ unsigned f2tf32(float f) {
    unsigned u; asm("cvt.rna.tf32.f32 %0, %1;" : "=r"(u) : "f"(f)); return u;
}
__device__ __forceinline__ void tf32_split(float v, unsigned& hi, unsigned& lo) {
    hi = f2tf32(v);
    lo = f2tf32(v - __uint_as_float(hi));
}

// D(m16n8, fp32) += A(m16k8, tf32) * B(k8n8, tf32)
#define MMA_TF32(d, a0, a1, a2, a3, b0, b1) \
    asm("mma.sync.aligned.m16n8k8.row.col.f32.tf32.tf32.f32 " \
        "{%0,%1,%2,%3},{%4,%5,%6,%7},{%8,%9},{%0,%1,%2,%3};" \
        : "+f"((d)[0]), "+f"((d)[1]), "+f"((d)[2]), "+f"((d)[3]) \
        : "r"(a0), "r"(a1), "r"(a2), "r"(a3), "r"(b0), "r"(b1))

// MMA mainloop over K=64 with 3xTF32 reading a precomputed L2 fragment table.
#define MMA_LOOP64T(acc, xs, wt)                                             \
    _Pragma("unroll")                                                        \
    for (int ks = 0; ks < 8; ks++) {                                         \
        int kk = ks * 8;                                                     \
        float a0 = xs[wr + gid    ][kk + tig    ];                           \
        float a1 = xs[wr + gid + 8][kk + tig    ];                           \
        float a2 = xs[wr + gid    ][kk + tig + 4];                           \
        float a3 = xs[wr + gid + 8][kk + tig + 4];                           \
        unsigned ah0, al0, ah1, al1, ah2, al2, ah3, al3;                     \
        tf32_split(a0, ah0, al0);                                            \
        tf32_split(a1, ah1, al1);                                            \
        tf32_split(a2, ah2, al2);                                            \
        tf32_split(a3, ah3, al3);                                            \
        _Pragma("unroll")                                                    \
        for (int nt = 0; nt < 8; nt++) {                                     \
            float4 wf = __ldg(&(wt)[(ks * 8 + nt) * 32 + lane]);             \
            unsigned bh0 = __float_as_uint(wf.x), bh1 = __float_as_uint(wf.y); \
            unsigned bl0 = __float_as_uint(wf.z), bl1 = __float_as_uint(wf.w); \
            MMA_TF32(acc[nt], ah0, ah1, ah2, ah3, bh0, bh1);                 \
            MMA_TF32(acc[nt], ah0, ah1, ah2, ah3, bl0, bl1);                 \
            MMA_TF32(acc[nt], al0, al1, al2, al3, bh0, bh1);                 \
        }                                                                    \
    }

// 2-channel gather-accumulate over one CSR row, 8 gathers in flight.
#define ROW_GATHER2(e, end, c0, a0, a1)                                      \
    {                                                                        \
        float u0 = 0.0f, u1 = 0.0f;                                          \
        for (; e + 8 <= end; e += 8) {                                       \
            int s0i = __ldg(&g_csr[e + 0]);                                  \
            int s1i = __ldg(&g_csr[e + 1]);                                  \
            int s2i = __ldg(&g_csr[e + 2]);                                  \
            int s3i = __ldg(&g_csr[e + 3]);                                  \
            int s4i = __ldg(&g_csr[e + 4]);                                  \
            int s5i = __ldg(&g_csr[e + 5]);                                  \
            int s6i = __ldg(&g_csr[e + 6]);                                  \
            int s7i = __ldg(&g_csr[e + 7]);                                  \
            float2 v0 = *(const float2*)&g_h[s0i * 64 + c0];                 \
            float2 v1 = *(const float2*)&g_h[s1i * 64 + c0];                 \
            float2 v2 = *(const float2*)&g_h[s2i * 64 + c0];                 \
            float2 v3 = *(const float2*)&g_h[s3i * 64 + c0];                 \
            float2 v4 = *(const float2*)&g_h[s4i * 64 + c0];                 \
            float2 v5 = *(const float2*)&g_h[s5i * 64 + c0];                 \
            float2 v6 = *(const float2*)&g_h[s6i * 64 + c0];                 \
            float2 v7 = *(const float2*)&g_h[s7i * 64 + c0];                 \
            a0 += (v0.x + v2.x) + (v4.x + v6.x);                             \
            a1 += (v0.y + v2.y) + (v4.y + v6.y);                             \
            u0 += (v1.x + v3.x) + (v5.x + v7.x);                             \
            u1 += (v1.y + v3.y) + (v5.y + v7.y);                             \
        }                                                                    \
        for (; e + 4 <= end; e += 4) {                                       \
            int sA = __ldg(&g_csr[e + 0]);                                   \
            int sB = __ldg(&g_csr[e + 1]);                                   \
            int sC = __ldg(&g_csr[e + 2]);                                   \
            int sD = __ldg(&g_csr[e + 3]);                                   \
            float2 vA = *(const float2*)&g_h[sA * 64 + c0];                  \
            float2 vB = *(const float2*)&g_h[sB * 64 + c0];                  \
            float2 vC = *(const float2*)&g_h[sC * 64 + c0];                  \
            float2 vD = *(const float2*)&g_h[sD * 64 + c0];                  \
            a0 += vA.x + vC.x; a1 += vA.y + vC.y;                            \
            u0 += vB.x + vD.x; u1 += vB.y + vD.y;                            \
        }                                                                    \
        for (; e < end; e++) {                                               \
            int sE = __ldg(&g_csr[e]);                                       \
            float2 v = *(const float2*)&g_h[sE * 64 + c0];                   \
            a0 += v.x; a1 += v.y;                                            \
        }                                                                    \
        a0 += u0; a1 += u1;                                                  \
    }

// ---------------------------------------------------------------------------
// prep0: fragment precompute (first 10240 threads) + counter/stat zeroing.
// ---------------------------------------------------------------------------
__global__ void k_prep0(const float* __restrict__ W1, const float* __restrict__ W2,
                        const float* __restrict__ Wf1, const float* __restrict__ Wf2,
                        int n) {
    int i = blockIdx.x * blockDim.x + threadIdx.x;
    if (i < 10240) {
        const float* W; float4* dst; int e;
        if (i < 4096)      { W = W1;  dst = g_wf1;  e = i; }
        else if (i < 6144) { W = W2;  dst = g_wf2;  e = i - 4096; }
        else if (i < 8192) { W = Wf1; dst = g_wff1; e = i - 6144; }
        else               { W = Wf2; dst = g_wff2; e = i - 8192; }
        int ks = e >> 8, nt = (e >> 5) & 7, ln = e & 31;
        int k0 = ks * 8 + (ln & 3);
        int nn = (ln >> 2) + 8 * nt;
        float w0 = W[k0 * 64 + nn];
        float w1 = W[(k0 + 4) * 64 + nn];
        unsigned h0, l0, h1, l1;
        tf32_split(w0, h0, l0);
        tf32_split(w1, h1, l1);
        dst[e] = make_float4(__uint_as_float(h0), __uint_as_float(h1),
                             __uint_as_float(l0), __uint_as_float(l1));
    }
    int st = gridDim.x * blockDim.x;
    for (int j = i; j < n; j += st) { g_cnt_out[j] = 0; g_cnt_in[j] = 0; }
    if (i < 256) g_stats[i] = 0.0f;
}

__global__ void k_deg(const int* __restrict__ src, const int* __restrict__ dst, int E) {
    int e = blockIdx.x * blockDim.x + threadIdx.x;
    if (e < E) {
        atomicAdd(&g_cnt_out[src[e]], 1);
        atomicAdd(&g_cnt_in [dst[e]], 1);
    }
}

__global__ void k_scan1(int n) {
    __shared__ int sh[256];
    int t = threadIdx.x, b = blockIdx.x;
    int base = b * 1024 + t * 4;
    int v0 = (base + 0 < n) ? g_cnt_in[base + 0] : 0;
    int v1 = (base + 1 < n) ? g_cnt_in[base + 1] : 0;
    int v2 = (base + 2 < n) ? g_cnt_in[base + 2] : 0;
    int v3 = (base + 3 < n) ? g_cnt_in[base + 3] : 0;
    int tsum = v0 + v1 + v2 + v3;
    sh[t] = tsum;
    __syncthreads();
    for (int o = 1; o < 256; o <<= 1) {
        int x = (t >= o) ? sh[t - o] : 0;
        __syncthreads();
        sh[t] += x;
        __syncthreads();
    }
    int excl = sh[t] - tsum;
    if (base + 0 < n) g_offs[base + 0] = excl;
    if (base + 1 < n) g_offs[base + 1] = excl + v0;
    if (base + 2 < n) g_offs[base + 2] = excl + v0 + v1;
    if (base + 3 < n) g_offs[base + 3] = excl + v0 + v1 + v2;
    if (t == 255) g_bsum[b] = sh[255];
}

__global__ void k_scan3(int n, int nblk) {
    __shared__ int bs[128];
    int t = threadIdx.x;
    if (t < 128) {
        int v = (t < nblk) ? g_bsum[t] : 0;
        bs[t] = v;
    }
    __syncthreads();
    #pragma unroll
    for (int o = 1; o < 128; o <<= 1) {
        int x = 0;
        if (t < 128 && t >= o) x = bs[t - o];
        __syncthreads();
        if (t < 128) bs[t] += x;
        __syncthreads();
    }
    int i = blockIdx.x * blockDim.x + t;
    if (i < n) {
        int chunk = i >> 10;
        int coff = (chunk == 0) ? 0 : bs[chunk - 1];
        int off = g_offs[i] + coff;
        g_offs[i] = off;
        g_cur[i]  = off;
        g_deg_in [i] = rsqrtf(fmaxf((float)g_cnt_in [i], 1.0f));
        g_deg_out[i] = rsqrtf(fmaxf((float)g_cnt_out[i], 1.0f));
    }
}

__global__ void k_fill(const int* __restrict__ src, const int* __restrict__ dst, int E) {
    int e = blockIdx.x * blockDim.x + threadIdx.x;
    if (e < E) {
        int d = dst[e];
        int p = atomicAdd(&g_cur[d], 1);
        g_csr[p] = src[e];
    }
}

// ---------------------------------------------------------------------------
// GEMM1 (tensor cores, K=128, frozen): 37.5us, tensor=48%.
// ---------------------------------------------------------------------------
__global__ __launch_bounds__(256, 3) void k_gemm1(const float* __restrict__ x, int n) {
    extern __shared__ __align__(16) char g1s[];
    float (*xraw)[128][36] = (float (*)[128][36])g1s;                 // [2][128][36]
    float4 (*wf)[1024]     = (float4 (*)[1024])(g1s + G1_XRAW_BYTES); // [2][1024]

    int t = threadIdx.x;
    int w = t >> 5, lane = t & 31;
    int gid = lane >> 2, tig = lane & 3;
    int row0 = blockIdx.x * 128;
    int wr = w * 16;

    auto load_chunk = [&](int c, int s) {
        int kc = c * 32;
        #pragma unroll
        for (int ii = 0; ii < 4; ii++) {
            int i = t + ii * 256;
            int r = i >> 3, c16 = (i & 7) * 4;
            int gr = row0 + r;
            cp16(&xraw[s][r][c16], &x[(long)gr * 128 + kc + c16], (gr < n) ? 16 : 0);
        }
        #pragma unroll
        for (int ii = 0; ii < 4; ii++) {
            int e = t + ii * 256;
            cp16(&wf[s][e], &g_wf1[c * 1024 + e], 16);
        }
        CP_COMMIT();
    };

    float acc[8][4];
    #pragma unroll
    for (int nt = 0; nt < 8; nt++)
        #pragma unroll
        for (int j = 0; j < 4; j++) acc[nt][j] = 0.0f;

    load_chunk(0, 0);
    for (int c = 0; c < 4; c++) {
        int s = c & 1;
        __syncthreads();
        if (c < 3) { load_chunk(c + 1, s ^ 1); CP_WAIT1(); }
        else       { CP_WAIT0(); }
        __syncthreads();
        #pragma unroll
        for (int ks = 0; ks < 4; ks++) {
            int kk = ks * 8;
            float a0 = xraw[s][wr + gid    ][kk + tig    ];
            float a1 = xraw[s][wr + gid + 8][kk + tig    ];
            float a2 = xraw[s][wr + gid    ][kk + tig + 4];
            float a3 = xraw[s][wr + gid + 8][kk + tig + 4];
            unsigned ah0, al0, ah1, al1, ah2, al2, ah3, al3;
            tf32_split(a0, ah0, al0);
            tf32_split(a1, ah1, al1);
            tf32_split(a2, ah2, al2);
            tf32_split(a3, ah3, al3);
            #pragma unroll
            for (int nt = 0; nt < 8; nt++) {
                float4 f = wf[s][(ks * 8 + nt) * 32 + lane];
                unsigned bh0 = __float_as_uint(f.x), bh1 = __float_as_uint(f.y);
                unsigned bl0 = __float_as_uint(f.z), bl1 = __float_as_uint(f.w);
                MMA_TF32(acc[nt], ah0, ah1, ah2, ah3, bh0, bh1);
                MMA_TF32(acc[nt], ah0, ah1, ah2, ah3, bl0, bl1);
                MMA_TF32(acc[nt], al0, al1, al2, al3, bh0, bh1);
            }
        }
    }
    int r_lo = row0 + wr + gid;
    int r_hi = r_lo + 8;
    float s_lo = (r_lo < n) ? rsqrtf(fmaxf((float)g_cnt_out[r_lo], 1.0f)) : 0.0f;
    float s_hi = (r_hi < n) ? rsqrtf(fmaxf((float)g_cnt_out[r_hi], 1.0f)) : 0.0f;
    #pragma unroll
    for (int nt = 0; nt < 8; nt++) {
        int cc = nt * 8 + tig * 2;
        if (r_lo < n)
            *(float2*)&g_h[r_lo * 64 + cc] = make_float2(acc[nt][0] * s_lo, acc[nt][1] * s_lo);
        if (r_hi < n)
            *(float2*)&g_h[r_hi * 64 + cc] = make_float2(acc[nt][2] * s_hi, acc[nt][3] * s_hi);
    }
}

// ---------------------------------------------------------------------------
// Aggregate 1 (CSR, R14 layout: warp per row, lane = 2 channels; 8-deep
// gather pipeline): g_v[d] = sum g_h[src]*deg_in + b1, plus BN1 stats.
// ---------------------------------------------------------------------------
__global__ void k_agg1(const float* __restrict__ b1, int n) {
    __shared__ float ss[64], sq[64];
    int t = threadIdx.x;
    if (t < 64) { ss[t] = 0.0f; sq[t] = 0.0f; }
    __syncthreads();
    int lane = t & 31;
    int gw = (blockIdx.x * blockDim.x + t) >> 5;
    int nw = (gridDim.x * blockDim.x) >> 5;
    int c0 = lane * 2;
    float bx = b1[c0], by = b1[c0 + 1];
    float s0 = 0, q0 = 0, s1 = 0, q1 = 0;
    for (int row = gw; row < n; row += nw) {
        int e = g_offs[row], end = g_cur[row];
        float a0 = 0.0f, a1 = 0.0f;
        ROW_GATHER2(e, end, c0, a0, a1);
        float sc = g_deg_in[row];
        a0 = fmaf(a0, sc, bx);
        a1 = fmaf(a1, sc, by);
        *(float2*)&g_v[row * 64 + c0] = make_float2(a0, a1);
        s0 += a0; q0 += a0 * a0;
        s1 += a1; q1 += a1 * a1;
    }
    atomicAdd(&ss[c0], s0);     atomicAdd(&ss[c0 + 1], s1);
    atomicAdd(&sq[c0], q0);     atomicAdd(&sq[c0 + 1], q1);
    __syncthreads();
    if (t < 64) { atomicAdd(&g_stats[t], ss[t]); atomicAdd(&g_stats[64 + t], sq[t]); }
}

// ---------------------------------------------------------------------------
// GEMM2 (tensor cores, K=64): g_h = (leaky(bn1(g_v)) * deg_out_scale) @ W2
// ---------------------------------------------------------------------------
__global__ __launch_bounds__(256, 3) void k_gemm2f(const float* __restrict__ bn1g,
        const float* __restrict__ bn1b, int n, float invn) {
    __shared__ __align__(16) float xs[128][68];
    __shared__ float ds[128];
    __shared__ float bnS[64], bnB[64];

    int t = threadIdx.x;
    int w = t >> 5, lane = t & 31;
    int gid = lane >> 2, tig = lane & 3;
    int row0 = blockIdx.x * 128;
    int wr = w * 16;

    if (t < 128) { int gr = row0 + t; ds[t] = (gr < n) ? g_deg_out[gr] : 0.0f; }
    if (t >= 128 && t < 192) {
        int c = t - 128;
        float mu  = g_stats[c] * invn;
        float var = g_stats[64 + c] * invn - mu * mu;
        float s = rsqrtf(var + 1e-5f) * bn1g[c];
        bnS[c] = s;
        bnB[c] = bn1b[c] - mu * s;
    }
    __syncthreads();

    #pragma unroll
    for (int ii = 0; ii < 32; ii++) {
        int i = t + ii * 256;
        int r = i >> 6, k = i & 63;
        int gr = row0 + r;
        float v = 0.0f;
        if (gr < n) v = lrelu(fmaf(g_v[gr * 64 + k], bnS[k], bnB[k])) * ds[r];
        xs[r][k] = v;
    }
    __syncthreads();

    float acc[8][4];
    #pragma unroll
    for (int nt = 0; nt < 8; nt++)
        #pragma unroll
        for (int j = 0; j < 4; j++) acc[nt][j] = 0.0f;
    MMA_LOOP64T(acc, xs, g_wf2);

    int r_lo = row0 + wr + gid;
    int r_hi = r_lo + 8;
    #pragma unroll
    for (int nt = 0; nt < 8; nt++) {
        int cc = nt * 8 + tig * 2;
        if (r_lo < n) *(float2*)&g_h[r_lo * 64 + cc] = make_float2(acc[nt][0], acc[nt][1]);
        if (r_hi < n) *(float2*)&g_h[r_hi * 64 + cc] = make_float2(acc[nt][2], acc[nt][3]);
    }
}

// ---------------------------------------------------------------------------
// Aggregate 2 (CSR, R14 layout + 8-deep pipeline): g_v[d] = relu(...)
// ---------------------------------------------------------------------------
__global__ void k_agg2(const float* __restrict__ b2, int n) {
    int t = threadIdx.x;
    int lane = t & 31;
    int gw = (blockIdx.x * blockDim.x + t) >> 5;
    int nw = (gridDim.x * blockDim.x) >> 5;
    int c0 = lane * 2;
    float bx = b2[c0], by = b2[c0 + 1];
    for (int row = gw; row < n; row += nw) {
        int e = g_offs[row], end = g_cur[row];
        float a0 = 0.0f, a1 = 0.0f;
        ROW_GATHER2(e, end, c0, a0, a1);
        float sc = g_deg_in[row];
        a0 = fmaxf(fmaf(a0, sc, bx), 0.0f);
        a1 = fmaxf(fmaf(a1, sc, by), 0.0f);
        *(float2*)&g_v[row * 64 + c0] = make_float2(a0, a1);
    }
}

// ---------------------------------------------------------------------------
// fc1 (tensor cores, K=64): emb = v[i0]-v[i1]; g_emb = emb @ fc1_w + b; BN2 stats.
// ---------------------------------------------------------------------------
__global__ __launch_bounds__(256, 3) void k_fc1(const int* __restrict__ bidx,
        const float* __restrict__ bias, int Bn) {
    __shared__ __align__(16) float xs[128][68];
    __shared__ int i0s[128], i1s[128];
    __shared__ float ss[64], sq[64], biass[64];

    int t = threadIdx.x;
    int w = t >> 5, lane = t & 31;
    int gid = lane >> 2, tig = lane & 3;
    int row0 = blockIdx.x * 128;
    int wr = w * 16;

    if (t < 128) {
        int gr = row0 + t;
        i0s[t] = (gr < Bn) ? bidx[gr] : 0;
        i1s[t] = (gr < Bn) ? bidx[Bn + gr] : 0;
    }
    if (t >= 128 && t < 192) {
        int c = t - 128;
        ss[c] = 0.0f; sq[c] = 0.0f; biass[c] = bias[c];
    }
    __syncthreads();

    #pragma unroll
    for (int ii = 0; ii < 32; ii++) {
        int i = t + ii * 256;
        int r = i >> 6, k = i & 63;
        float v = 0.0f;
        if (row0 + r < Bn) v = g_v[i0s[r] * 64 + k] - g_v[i1s[r] * 64 + k];
        xs[r][k] = v;
    }
    __syncthreads();

    float acc[8][4];
    #pragma unroll
    for (int nt = 0; nt < 8; nt++)
        #pragma unroll
        for (int j = 0; j < 4; j++) acc[nt][j] = 0.0f;
    MMA_LOOP64T(acc, xs, g_wff1);

    int r_lo = row0 + wr + gid;
    int r_hi = r_lo + 8;
    bool ok_lo = r_lo < Bn, ok_hi = r_hi < Bn;
    #pragma unroll
    for (int nt = 0; nt < 8; nt++) {
        int cc = nt * 8 + tig * 2;
        float b0 = biass[cc], b1 = biass[cc + 1];
        float sa0 = 0.0f, qa0 = 0.0f, sa1 = 0.0f, qa1 = 0.0f;
        if (ok_lo) {
            float a0 = acc[nt][0] + b0, a1 = acc[nt][1] + b1;
            *(float2*)&g_emb[r_lo * 64 + cc] = make_float2(a0, a1);
            sa0 += a0; qa0 += a0 * a0; sa1 += a1; qa1 += a1 * a1;
        }
        if (ok_hi) {
            float a2 = acc[nt][2] + b0, a3 = acc[nt][3] + b1;
            *(float2*)&g_emb[r_hi * 64 + cc] = make_float2(a2, a3);
            sa0 += a2; qa0 += a2 * a2; sa1 += a3; qa1 += a3 * a3;
        }
        atomicAdd(&ss[cc], sa0);     atomicAdd(&sq[cc], qa0);
        atomicAdd(&ss[cc + 1], sa1); atomicAdd(&sq[cc + 1], qa1);
    }
    __syncthreads();
    if (t < 64) {
        atomicAdd(&g_stats[128 + t], ss[t]);
        atomicAdd(&g_stats[192 + t], sq[t]);
    }
}

// ---------------------------------------------------------------------------
// Final (tensor cores, K=64): y = leaky(bn2(g_emb)); z = leaky(y @ fc2_w + b2f);
// out = z @ fc3_w + b3. Quad-shuffle reduction for the fc3 dot.
// ---------------------------------------------------------------------------
__global__ __launch_bounds__(256, 3) void k_final(const float* __restrict__ b2f,
        const float* __restrict__ w3, const float* __restrict__ b3,
        const float* __restrict__ g2, const float* __restrict__ bb2,
        int Bn, float invB, float* __restrict__ out) {
    __shared__ __align__(16) float xs[128][68];
    __shared__ float bnS[64], bnB[64], w3s[64], b2fs[64];

    int t = threadIdx.x;
    int w = t >> 5, lane = t & 31;
    int gid = lane >> 2, tig = lane & 3;
    int row0 = blockIdx.x * 128;
    int wr = w * 16;

    if (t < 64) {
        float mu  = g_stats[128 + t] * invB;
        float var = g_stats[192 + t] * invB - mu * mu;
        float s = rsqrtf(var + 1e-5f) * g2[t];
        bnS[t] = s;
        bnB[t] = bb2[t] - mu * s;
        w3s[t] = w3[t];
        b2fs[t] = b2f[t];
    }
    __syncthreads();

    #pragma unroll
    for (int ii = 0; ii < 32; ii++) {
        int i = t + ii * 256;
        int r = i >> 6, k = i & 63;
        int gr = row0 + r;
        float v = 0.0f;
        if (gr < Bn) v = lrelu(fmaf(g_emb[gr * 64 + k], bnS[k], bnB[k]));
        xs[r][k] = v;
    }
    __syncthreads();

    float acc[8][4];
    #pragma unroll
    for (int nt = 0; nt < 8; nt++)
        #pragma unroll
        for (int j = 0; j < 4; j++) acc[nt][j] = 0.0f;
    MMA_LOOP64T(acc, xs, g_wff2);

    float p_lo = 0.0f, p_hi = 0.0f;
    #pragma unroll
    for (int nt = 0; nt < 8; nt++) {
        int cc = nt * 8 + tig * 2;
        float b0 = b2fs[cc], b1 = b2fs[cc + 1];
        float w0 = w3s[cc],  w1 = w3s[cc + 1];
        p_lo = fmaf(lrelu(acc[nt][0] + b0), w0, p_lo);
        p_lo = fmaf(lrelu(acc[nt][1] + b1), w1, p_lo);
        p_hi = fmaf(lrelu(acc[nt][2] + b0), w0, p_hi);
        p_hi = fmaf(lrelu(acc[nt][3] + b1), w1, p_hi);
    }
    #pragma unroll
    for (int o = 1; o < 4; o <<= 1) {
        p_lo += __shfl_xor_sync(0xffffffffu, p_lo, o);
        p_hi += __shfl_xor_sync(0xffffffffu, p_hi, o);
    }
    int r_lo = row0 + wr + gid;
    int r_hi = r_lo + 8;
    if (tig == 0) {
        float bb = b3[0];
        if (r_lo < Bn) out[r_lo] = p_lo + bb;
        if (r_hi < Bn) out[r_hi] = p_hi + bb;
    }
}

// ---------------------------------------------------------------------------
extern "C" void kernel_launch(void* const* d_in, const int* in_sizes, int n_in,
                              void* d_out, int out_size) {
    const float* x    = (const float*)d_in[0];
    const int*   src  = (const int*)  d_in[1];
    const int*   dst  = (const int*)  d_in[2];
    const int*   bidx = (const int*)  d_in[3];
    const float* W1   = (const float*)d_in[4];
    const float* b1   = (const float*)d_in[5];
    const float* W2   = (const float*)d_in[6];
    const float* b2   = (const float*)d_in[7];
    const float* fc1w = (const float*)d_in[8];
    const float* fc1b = (const float*)d_in[9];
    const float* fc2w = (const float*)d_in[10];
    const float* fc2b = (const float*)d_in[11];
    const float* fc3w = (const float*)d_in[12];
    const float* fc3b = (const float*)d_in[13];
    const float* bn1g = (const float*)d_in[14];
    const float* bn1b = (const float*)d_in[15];
    const float* bn2g = (const float*)d_in[16];
    const float* bn2b = (const float*)d_in[17];

    int n  = in_sizes[0] / 128;   // nodes
    int E  = in_sizes[1];         // edges
    int Bn = in_sizes[3] / 2;     // pairs
    float* out = (float*)d_out;

    int eb  = (E + 255) / 256;
    int nb  = (n + 255) / 256;
    int nsb = (n + 1023) / 1024;
    int gb  = (n + 127) / 128;
    int gbB = (Bn + 127) / 128;

    static bool attr_done = false;
    if (!attr_done) {
        cudaFuncSetAttribute(k_gemm1, cudaFuncAttributeMaxDynamicSharedMemorySize, G1_SMEM);
        attr_done = true;
    }

    // 11 launches; gemm1 at slot 4 (profiled)
    k_prep0<<<512, 256>>>(W1, W2, fc1w, fc2w, n);
    k_deg  <<<eb, 256>>>(src, dst, E);
    k_scan1<<<nsb, 256>>>(n);
    k_gemm1<<<gb, 256, G1_SMEM>>>(x, n);
    k_scan3<<<nb, 256>>>(n, nsb);
    k_fill <<<eb, 256>>>(src, dst, E);

    // conv1 aggregation
    k_agg1 <<<1184, 256>>>(b1, n);

    // conv2 (bn1 + leaky fused into gemm2 load)
    k_gemm2f<<<gb, 256>>>(bn1g, bn1b, n, 1.0f / n);
    k_agg2  <<<1184, 256>>>(b2, n);

    // head
    k_fc1  <<<gbB, 256>>>(bidx, fc1b, Bn);
    k_final<<<gbB, 256>>>(fc2b, fc3w, fc3b, bn2g, bn2b, Bn, 1.0f / Bn, out);
}

// round 17
// speedup vs baseline: 1.0618x; 1.0078x over previous
#include <cuda_runtime.h>

// Shapes fixed per reference: N=100000, E=1200000, B=100000, IDIM=128, H1=H2=64.
#define NMAX 100000
#define EMAX 1200000
#define BMAX 100000

// gemm1 dynamic smem: xraw[2][128][36] + wf[2][1024] float4 (both double-buffered)
#define G1_XRAW_BYTES (2 * 128 * 36 * 4)   // 36864
#define G1_WF_BYTES   (2 * 1024 * 16)      // 32768
#define G1_SMEM       (G1_XRAW_BYTES + G1_WF_BYTES)  // 69632

__device__ float g_deg_in [NMAX];     // rsqrt(max(in_deg,1))
__device__ float g_deg_out[NMAX];     // rsqrt(max(out_deg,1))
__device__ int   g_cnt_out[NMAX];
__device__ int   g_cnt_in [NMAX];
__device__ int   g_offs   [NMAX];     // CSR row starts (by dst)
__device__ int   g_cur    [NMAX];     // fill cursors; == row end after fill
__device__ int   g_bsum   [128];      // scan1 raw block sums
__device__ int   g_csr    [EMAX];     // src ids grouped by dst
__device__ float g_h  [NMAX * 64];    // pre-aggregation features
__device__ float g_v  [NMAX * 64];    // node features v1 / v2
__device__ float g_emb[BMAX * 64];    // fc1 output (pre-BN2)
__device__ float g_stats[256];        // [0:64) sum1 [64:128) sq1 [128:192) sum2 [192:256) sq2

// Precomputed tf32 hi/lo B-fragment tables (built once per replay by k_prep0).
__device__ float4 g_wf1 [4096];   // W1  (K=128)
__device__ float4 g_wf2 [2048];   // W2  (K=64)
__device__ float4 g_wff1[2048];   // fc1_w
__device__ float4 g_wff2[2048];   // fc2_w

__device__ __forceinline__ float lrelu(float v) { return v > 0.0f ? v : 0.01f * v; }

// cp.async helpers (16B, cache-global; src_sz=0 -> zero-fill dst)
__device__ __forceinline__ void cp16(void* dst_smem, const void* src_gmem, int src_sz) {
    unsigned ds = (unsigned)__cvta_generic_to_shared(dst_smem);
    asm volatile("cp.async.cg.shared.global [%0], [%1], 16, %2;\n"
                 :: "r"(ds), "l"(src_gmem), "r"(src_sz));
}
#define CP_COMMIT() asm volatile("cp.async.commit_group;\n" ::: "memory")
#define CP_WAIT1()  asm volatile("cp.async.wait_group 1;\n" ::: "memory")
#define CP_WAIT0()  asm volatile("cp.async.wait_group 0;\n" ::: "memory")

// tf32 helpers: hi = round-to-nearest tf32; lo = v - hi (3xTF32 split).
__device__ __forceinline__ unsigned f2tf32(float f) {
    unsigned u; asm("cvt.rna.tf32.f32 %0, %1;" : "=r"(u) : "f"(f)); return u;
}
__device__ __forceinline__ void tf32_split(float v, unsigned& hi, unsigned& lo) {
    hi = f2tf32(v);
    lo = f2tf32(v - __uint_as_float(hi));
}

// D(m16n8, fp32) += A(m16k8, tf32) * B(k8n8, tf32)
#define MMA_TF32(d, a0, a1, a2, a3, b0, b1) \
    asm("mma.sync.aligned.m16n8k8.row.col.f32.tf32.tf32.f32 " \
        "{%0,%1,%2,%3},{%4,%5,%6,%7},{%8,%9},{%0,%1,%2,%3};" \
        : "+f"((d)[0]), "+f"((d)[1]), "+f"((d)[2]), "+f"((d)[3]) \
        : "r"(a0), "r"(a1), "r"(a2), "r"(a3), "r"(b0), "r"(b1))

// MMA mainloop over K=64 with 3xTF32 reading a precomputed L2 fragment table.
#define MMA_LOOP64T(acc, xs, wt)                                             \
    _Pragma("unroll")                                                        \
    for (int ks = 0; ks < 8; ks++) {                                         \
        int kk = ks * 8;                                                     \
        float a0 = xs[wr + gid    ][kk + tig    ];                           \
        float a1 = xs[wr + gid + 8][kk + tig    ];                           \
        float a2 = xs[wr + gid    ][kk + tig + 4];                           \
        float a3 = xs[wr + gid + 8][kk + tig + 4];                           \
        unsigned ah0, al0, ah1, al1, ah2, al2, ah3, al3;                     \
        tf32_split(a0, ah0, al0);                                            \
        tf32_split(a1, ah1, al1);                                            \
        tf32_split(a2, ah2, al2);                                            \
        tf32_split(a3, ah3, al3);                                            \
        _Pragma("unroll")                                                    \
        for (int nt = 0; nt < 8; nt++) {                                     \
            float4 wf = __ldg(&(wt)[(ks * 8 + nt) * 32 + lane]);             \
            unsigned bh0 = __float_as_uint(wf.x), bh1 = __float_as_uint(wf.y); \
            unsigned bl0 = __float_as_uint(wf.z), bl1 = __float_as_uint(wf.w); \
            MMA_TF32(acc[nt], ah0, ah1, ah2, ah3, bh0, bh1);                 \
            MMA_TF32(acc[nt], ah0, ah1, ah2, ah3, bl0, bl1);                 \
            MMA_TF32(acc[nt], al0, al1, al2, al3, bh0, bh1);                 \
        }                                                                    \
    }

// 2-channel gather-accumulate over one CSR row, 8 gathers in flight.
#define ROW_GATHER2(e, end, c0, a0, a1)                                      \
    {                                                                        \
        float u0 = 0.0f, u1 = 0.0f;                                          \
        for (; e + 8 <= end; e += 8) {                                       \
            int s0i = __ldg(&g_csr[e + 0]);                                  \
            int s1i = __ldg(&g_csr[e + 1]);                                  \
            int s2i = __ldg(&g_csr[e + 2]);                                  \
            int s3i = __ldg(&g_csr[e + 3]);                                  \
            int s4i = __ldg(&g_csr[e + 4]);                                  \
            int s5i = __ldg(&g_csr[e + 5]);                                  \
            int s6i = __ldg(&g_csr[e + 6]);                                  \
            int s7i = __ldg(&g_csr[e + 7]);                                  \
            float2 v0 = *(const float2*)&g_h[s0i * 64 + c0];                 \
            float2 v1 = *(const float2*)&g_h[s1i * 64 + c0];                 \
            float2 v2 = *(const float2*)&g_h[s2i * 64 + c0];                 \
            float2 v3 = *(const float2*)&g_h[s3i * 64 + c0];                 \
            float2 v4 = *(const float2*)&g_h[s4i * 64 + c0];                 \
            float2 v5 = *(const float2*)&g_h[s5i * 64 + c0];                 \
            float2 v6 = *(const float2*)&g_h[s6i * 64 + c0];                 \
            float2 v7 = *(const float2*)&g_h[s7i * 64 + c0];                 \
            a0 += (v0.x + v2.x) + (v4.x + v6.x);                             \
            a1 += (v0.y + v2.y) + (v4.y + v6.y);                             \
            u0 += (v1.x + v3.x) + (v5.x + v7.x);                             \
            u1 += (v1.y + v3.y) + (v5.y + v7.y);                             \
        }                                                                    \
        for (; e + 4 <= end; e += 4) {                                       \
            int sA = __ldg(&g_csr[e + 0]);                                   \
            int sB = __ldg(&g_csr[e + 1]);                                   \
            int sC = __ldg(&g_csr[e + 2]);                                   \
            int sD = __ldg(&g_csr[e + 3]);                                   \
            float2 vA = *(const float2*)&g_h[sA * 64 + c0];                  \
            float2 vB = *(const float2*)&g_h[sB * 64 + c0];                  \
            float2 vC = *(const float2*)&g_h[sC * 64 + c0];                  \
            float2 vD = *(const float2*)&g_h[sD * 64 + c0];                  \
            a0 += vA.x + vC.x; a1 += vA.y + vC.y;                            \
            u0 += vB.x + vD.x; u1 += vB.y + vD.y;                            \
        }                                                                    \
        for (; e < end; e++) {                                               \
            int sE = __ldg(&g_csr[e]);                                       \
            float2 v = *(const float2*)&g_h[sE * 64 + c0];                   \
            a0 += v.x; a1 += v.y;                                            \
        }                                                                    \
        a0 += u0; a1 += u1;                                                  \
    }

// ---------------------------------------------------------------------------
// prep0: fragment precompute (first 10240 threads) + counter/stat zeroing.
// ---------------------------------------------------------------------------
__global__ void k_prep0(const float* __restrict__ W1, const float* __restrict__ W2,
                        const float* __restrict__ Wf1, const float* __restrict__ Wf2,
                        int n) {
    int i = blockIdx.x * blockDim.x + threadIdx.x;
    if (i < 10240) {
        const float* W; float4* dst; int e;
        if (i < 4096)      { W = W1;  dst = g_wf1;  e = i; }
        else if (i < 6144) { W = W2;  dst = g_wf2;  e = i - 4096; }
        else if (i < 8192) { W = Wf1; dst = g_wff1; e = i - 6144; }
        else               { W = Wf2; dst = g_wff2; e = i - 8192; }
        int ks = e >> 8, nt = (e >> 5) & 7, ln = e & 31;
        int k0 = ks * 8 + (ln & 3);
        int nn = (ln >> 2) + 8 * nt;
        float w0 = W[k0 * 64 + nn];
        float w1 = W[(k0 + 4) * 64 + nn];
        unsigned h0, l0, h1, l1;
        tf32_split(w0, h0, l0);
        tf32_split(w1, h1, l1);
        dst[e] = make_float4(__uint_as_float(h0), __uint_as_float(h1),
                             __uint_as_float(l0), __uint_as_float(l1));
    }
    int st = gridDim.x * blockDim.x;
    for (int j = i; j < n; j += st) { g_cnt_out[j] = 0; g_cnt_in[j] = 0; }
    if (i < 256) g_stats[i] = 0.0f;
}

__global__ void k_deg(const int* __restrict__ src, const int* __restrict__ dst, int E) {
    int e = blockIdx.x * blockDim.x + threadIdx.x;
    if (e < E) {
        atomicAdd(&g_cnt_out[src[e]], 1);
        atomicAdd(&g_cnt_in [dst[e]], 1);
    }
}

__global__ void k_scan1(int n) {
    __shared__ int sh[256];
    int t = threadIdx.x, b = blockIdx.x;
    int base = b * 1024 + t * 4;
    int v0 = (base + 0 < n) ? g_cnt_in[base + 0] : 0;
    int v1 = (base + 1 < n) ? g_cnt_in[base + 1] : 0;
    int v2 = (base + 2 < n) ? g_cnt_in[base + 2] : 0;
    int v3 = (base + 3 < n) ? g_cnt_in[base + 3] : 0;
    int tsum = v0 + v1 + v2 + v3;
    sh[t] = tsum;
    __syncthreads();
    for (int o = 1; o < 256; o <<= 1) {
        int x = (t >= o) ? sh[t - o] : 0;
        __syncthreads();
        sh[t] += x;
        __syncthreads();
    }
    int excl = sh[t] - tsum;
    if (base + 0 < n) g_offs[base + 0] = excl;
    if (base + 1 < n) g_offs[base + 1] = excl + v0;
    if (base + 2 < n) g_offs[base + 2] = excl + v0 + v1;
    if (base + 3 < n) g_offs[base + 3] = excl + v0 + v1 + v2;
    if (t == 255) g_bsum[b] = sh[255];
}

__global__ void k_scan3(int n, int nblk) {
    __shared__ int bs[128];
    int t = threadIdx.x;
    if (t < 128) {
        int v = (t < nblk) ? g_bsum[t] : 0;
        bs[t] = v;
    }
    __syncthreads();
    #pragma unroll
    for (int o = 1; o < 128; o <<= 1) {
        int x = 0;
        if (t < 128 && t >= o) x = bs[t - o];
        __syncthreads();
        if (t < 128) bs[t] += x;
        __syncthreads();
    }
    int i = blockIdx.x * blockDim.x + t;
    if (i < n) {
        int chunk = i >> 10;
        int coff = (chunk == 0) ? 0 : bs[chunk - 1];
        int off = g_offs[i] + coff;
        g_offs[i] = off;
        g_cur[i]  = off;
        g_deg_in [i] = rsqrtf(fmaxf((float)g_cnt_in [i], 1.0f));
        g_deg_out[i] = rsqrtf(fmaxf((float)g_cnt_out[i], 1.0f));
    }
}

__global__ void k_fill(const int* __restrict__ src, const int* __restrict__ dst, int E) {
    int e = blockIdx.x * blockDim.x + threadIdx.x;
    if (e < E) {
        int d = dst[e];
        int p = atomicAdd(&g_cur[d], 1);
        g_csr[p] = src[e];
    }
}

// ---------------------------------------------------------------------------
// GEMM1 (tensor cores, K=128, frozen): 37.5us, tensor=48%.
// ---------------------------------------------------------------------------
__global__ __launch_bounds__(256, 3) void k_gemm1(const float* __restrict__ x, int n) {
    extern __shared__ __align__(16) char g1s[];
    float (*xraw)[128][36] = (float (*)[128][36])g1s;                 // [2][128][36]
    float4 (*wf)[1024]     = (float4 (*)[1024])(g1s + G1_XRAW_BYTES); // [2][1024]

    int t = threadIdx.x;
    int w = t >> 5, lane = t & 31;
    int gid = lane >> 2, tig = lane & 3;
    int row0 = blockIdx.x * 128;
    int wr = w * 16;

    auto load_chunk = [&](int c, int s) {
        int kc = c * 32;
        #pragma unroll
        for (int ii = 0; ii < 4; ii++) {
            int i = t + ii * 256;
            int r = i >> 3, c16 = (i & 7) * 4;
            int gr = row0 + r;
            cp16(&xraw[s][r][c16], &x[(long)gr * 128 + kc + c16], (gr < n) ? 16 : 0);
        }
        #pragma unroll
        for (int ii = 0; ii < 4; ii++) {
            int e = t + ii * 256;
            cp16(&wf[s][e], &g_wf1[c * 1024 + e], 16);
        }
        CP_COMMIT();
    };

    float acc[8][4];
    #pragma unroll
    for (int nt = 0; nt < 8; nt++)
        #pragma unroll
        for (int j = 0; j < 4; j++) acc[nt][j] = 0.0f;

    load_chunk(0, 0);
    for (int c = 0; c < 4; c++) {
        int s = c & 1;
        __syncthreads();
        if (c < 3) { load_chunk(c + 1, s ^ 1); CP_WAIT1(); }
        else       { CP_WAIT0(); }
        __syncthreads();
        #pragma unroll
        for (int ks = 0; ks < 4; ks++) {
            int kk = ks * 8;
            float a0 = xraw[s][wr + gid    ][kk + tig    ];
            float a1 = xraw[s][wr + gid + 8][kk + tig    ];
            float a2 = xraw[s][wr + gid    ][kk + tig + 4];
            float a3 = xraw[s][wr + gid + 8][kk + tig + 4];
            unsigned ah0, al0, ah1, al1, ah2, al2, ah3, al3;
            tf32_split(a0, ah0, al0);
            tf32_split(a1, ah1, al1);
            tf32_split(a2, ah2, al2);
            tf32_split(a3, ah3, al3);
            #pragma unroll
            for (int nt = 0; nt < 8; nt++) {
                float4 f = wf[s][(ks * 8 + nt) * 32 + lane];
                unsigned bh0 = __float_as_uint(f.x), bh1 = __float_as_uint(f.y);
                unsigned bl0 = __float_as_uint(f.z), bl1 = __float_as_uint(f.w);
                MMA_TF32(acc[nt], ah0, ah1, ah2, ah3, bh0, bh1);
                MMA_TF32(acc[nt], ah0, ah1, ah2, ah3, bl0, bl1);
                MMA_TF32(acc[nt], al0, al1, al2, al3, bh0, bh1);
            }
        }
    }
    int r_lo = row0 + wr + gid;
    int r_hi = r_lo + 8;
    float s_lo = (r_lo < n) ? rsqrtf(fmaxf((float)g_cnt_out[r_lo], 1.0f)) : 0.0f;
    float s_hi = (r_hi < n) ? rsqrtf(fmaxf((float)g_cnt_out[r_hi], 1.0f)) : 0.0f;
    #pragma unroll
    for (int nt = 0; nt < 8; nt++) {
        int cc = nt * 8 + tig * 2;
        if (r_lo < n)
            *(float2*)&g_h[r_lo * 64 + cc] = make_float2(acc[nt][0] * s_lo, acc[nt][1] * s_lo);
        if (r_hi < n)
            *(float2*)&g_h[r_hi * 64 + cc] = make_float2(acc[nt][2] * s_hi, acc[nt][3] * s_hi);
    }
}

// ---------------------------------------------------------------------------
// Aggregate 1 (CSR): g_v[d] = sum g_h[src]*deg_in + b1, plus BN1 stats.
// ---------------------------------------------------------------------------
__global__ void k_agg1(const float* __restrict__ b1, int n) {
    __shared__ float ss[64], sq[64];
    int t = threadIdx.x;
    if (t < 64) { ss[t] = 0.0f; sq[t] = 0.0f; }
    __syncthreads();
    int lane = t & 31;
    int gw = (blockIdx.x * blockDim.x + t) >> 5;
    int nw = (gridDim.x * blockDim.x) >> 5;
    int c0 = lane * 2;
    float bx = b1[c0], by = b1[c0 + 1];
    float s0 = 0, q0 = 0, s1 = 0, q1 = 0;
    for (int row = gw; row < n; row += nw) {
        int e = g_offs[row], end = g_cur[row];
        float a0 = 0.0f, a1 = 0.0f;
        ROW_GATHER2(e, end, c0, a0, a1);
        float sc = g_deg_in[row];
        a0 = fmaf(a0, sc, bx);
        a1 = fmaf(a1, sc, by);
        *(float2*)&g_v[row * 64 + c0] = make_float2(a0, a1);
        s0 += a0; q0 += a0 * a0;
        s1 += a1; q1 += a1 * a1;
    }
    atomicAdd(&ss[c0], s0);     atomicAdd(&ss[c0 + 1], s1);
    atomicAdd(&sq[c0], q0);     atomicAdd(&sq[c0 + 1], q1);
    __syncthreads();
    if (t < 64) { atomicAdd(&g_stats[t], ss[t]); atomicAdd(&g_stats[64 + t], sq[t]); }
}

// ---------------------------------------------------------------------------
// GEMM2 (tensor cores, K=64): g_h = (leaky(bn1(g_v)) * deg_out_scale) @ W2
// ---------------------------------------------------------------------------
__global__ __launch_bounds__(256, 3) void k_gemm2f(const float* __restrict__ bn1g,
        const float* __restrict__ bn1b, int n, float invn) {
    __shared__ __align__(16) float xs[128][68];
    __shared__ float ds[128];
    __shared__ float bnS[64], bnB[64];

    int t = threadIdx.x;
    int w = t >> 5, lane = t & 31;
    int gid = lane >> 2, tig = lane & 3;
    int row0 = blockIdx.x * 128;
    int wr = w * 16;

    if (t < 128) { int gr = row0 + t; ds[t] = (gr < n) ? g_deg_out[gr] : 0.0f; }
    if (t >= 128 && t < 192) {
        int c = t - 128;
        float mu  = g_stats[c] * invn;
        float var = g_stats[64 + c] * invn - mu * mu;
        float s = rsqrtf(var + 1e-5f) * bn1g[c];
        bnS[c] = s;
        bnB[c] = bn1b[c] - mu * s;
    }
    __syncthreads();

    #pragma unroll
    for (int ii = 0; ii < 32; ii++) {
        int i = t + ii * 256;
        int r = i >> 6, k = i & 63;
        int gr = row0 + r;
        float v = 0.0f;
        if (gr < n) v = lrelu(fmaf(g_v[gr * 64 + k], bnS[k], bnB[k])) * ds[r];
        xs[r][k] = v;
    }
    __syncthreads();

    float acc[8][4];
    #pragma unroll
    for (int nt = 0; nt < 8; nt++)
        #pragma unroll
        for (int j = 0; j < 4; j++) acc[nt][j] = 0.0f;
    MMA_LOOP64T(acc, xs, g_wf2);

    int r_lo = row0 + wr + gid;
    int r_hi = r_lo + 8;
    #pragma unroll
    for (int nt = 0; nt < 8; nt++) {
        int cc = nt * 8 + tig * 2;
        if (r_lo < n) *(float2*)&g_h[r_lo * 64 + cc] = make_float2(acc[nt][0], acc[nt][1]);
        if (r_hi < n) *(float2*)&g_h[r_hi * 64 + cc] = make_float2(acc[nt][2], acc[nt][3]);
    }
}

// ---------------------------------------------------------------------------
// Aggregate 2 (CSR): g_v[d] = relu(sum g_h[src]*deg_in + b2)
// ---------------------------------------------------------------------------
__global__ void k_agg2(const float* __restrict__ b2, int n) {
    int t = threadIdx.x;
    int lane = t & 31;
    int gw = (blockIdx.x * blockDim.x + t) >> 5;
    int nw = (gridDim.x * blockDim.x) >> 5;
    int c0 = lane * 2;
    float bx = b2[c0], by = b2[c0 + 1];
    for (int row = gw; row < n; row += nw) {
        int e = g_offs[row], end = g_cur[row];
        float a0 = 0.0f, a1 = 0.0f;
        ROW_GATHER2(e, end, c0, a0, a1);
        float sc = g_deg_in[row];
        a0 = fmaxf(fmaf(a0, sc, bx), 0.0f);
        a1 = fmaxf(fmaf(a1, sc, by), 0.0f);
        *(float2*)&g_v[row * 64 + c0] = make_float2(a0, a1);
    }
}

// ---------------------------------------------------------------------------
// fc1 (tensor cores, K=64): emb = v[i0]-v[i1]; g_emb = emb @ fc1_w + b; BN2 stats.
// ---------------------------------------------------------------------------
__global__ __launch_bounds__(256, 3) void k_fc1(const int* __restrict__ bidx,
        const float* __restrict__ bias, int Bn) {
    __shared__ __align__(16) float xs[128][68];
    __shared__ int i0s[128], i1s[128];
    __shared__ float ss[64], sq[64], biass[64];

    int t = threadIdx.x;
    int w = t >> 5, lane = t & 31;
    int gid = lane >> 2, tig = lane & 3;
    int row0 = blockIdx.x * 128;
    int wr = w * 16;

    if (t < 128) {
        int gr = row0 + t;
        i0s[t] = (gr < Bn) ? bidx[gr] : 0;
        i1s[t] = (gr < Bn) ? bidx[Bn + gr] : 0;
    }
    if (t >= 128 && t < 192) {
        int c = t - 128;
        ss[c] = 0.0f; sq[c] = 0.0f; biass[c] = bias[c];
    }
    __syncthreads();

    #pragma unroll
    for (int ii = 0; ii < 32; ii++) {
        int i = t + ii * 256;
        int r = i >> 6, k = i & 63;
        float v = 0.0f;
        if (row0 + r < Bn) v = g_v[i0s[r] * 64 + k] - g_v[i1s[r] * 64 + k];
        xs[r][k] = v;
    }
    __syncthreads();

    float acc[8][4];
    #pragma unroll
    for (int nt = 0; nt < 8; nt++)
        #pragma unroll
        for (int j = 0; j < 4; j++) acc[nt][j] = 0.0f;
    MMA_LOOP64T(acc, xs, g_wff1);

    int r_lo = row0 + wr + gid;
    int r_hi = r_lo + 8;
    bool ok_lo = r_lo < Bn, ok_hi = r_hi < Bn;
    #pragma unroll
    for (int nt = 0; nt < 8; nt++) {
        int cc = nt * 8 + tig * 2;
        float b0 = biass[cc], b1 = biass[cc + 1];
        float sa0 = 0.0f, qa0 = 0.0f, sa1 = 0.0f, qa1 = 0.0f;
        if (ok_lo) {
            float a0 = acc[nt][0] + b0, a1 = acc[nt][1] + b1;
            *(float2*)&g_emb[r_lo * 64 + cc] = make_float2(a0, a1);
            sa0 += a0; qa0 += a0 * a0; sa1 += a1; qa1 += a1 * a1;
        }
        if (ok_hi) {
            float a2 = acc[nt][2] + b0, a3 = acc[nt][3] + b1;
            *(float2*)&g_emb[r_hi * 64 + cc] = make_float2(a2, a3);
            sa0 += a2; qa0 += a2 * a2; sa1 += a3; qa1 += a3 * a3;
        }
        atomicAdd(&ss[cc], sa0);     atomicAdd(&sq[cc], qa0);
        atomicAdd(&ss[cc + 1], sa1); atomicAdd(&sq[cc + 1], qa1);
    }
    __syncthreads();
    if (t < 64) {
        atomicAdd(&g_stats[128 + t], ss[t]);
        atomicAdd(&g_stats[192 + t], sq[t]);
    }
}

// ---------------------------------------------------------------------------
// Final (tensor cores, K=64): y = leaky(bn2(g_emb)); z = leaky(y @ fc2_w + b2f);
// out = z @ fc3_w + b3. Quad-shuffle reduction for the fc3 dot.
// ---------------------------------------------------------------------------
__global__ __launch_bounds__(256, 3) void k_final(const float* __restrict__ b2f,
        const float* __restrict__ w3, const float* __restrict__ b3,
        const float* __restrict__ g2, const float* __restrict__ bb2,
        int Bn, float invB, float* __restrict__ out) {
    __shared__ __align__(16) float xs[128][68];
    __shared__ float bnS[64], bnB[64], w3s[64], b2fs[64];

    int t = threadIdx.x;
    int w = t >> 5, lane = t & 31;
    int gid = lane >> 2, tig = lane & 3;
    int row0 = blockIdx.x * 128;
    int wr = w * 16;

    if (t < 64) {
        float mu  = g_stats[128 + t] * invB;
        float var = g_stats[192 + t] * invB - mu * mu;
        float s = rsqrtf(var + 1e-5f) * g2[t];
        bnS[t] = s;
        bnB[t] = bb2[t] - mu * s;
        w3s[t] = w3[t];
        b2fs[t] = b2f[t];
    }
    __syncthreads();

    #pragma unroll
    for (int ii = 0; ii < 32; ii++) {
        int i = t + ii * 256;
        int r = i >> 6, k = i & 63;
        int gr = row0 + r;
        float v = 0.0f;
        if (gr < Bn) v = lrelu(fmaf(g_emb[gr * 64 + k], bnS[k], bnB[k]));
        xs[r][k] = v;
    }
    __syncthreads();

    float acc[8][4];
    #pragma unroll
    for (int nt = 0; nt < 8; nt++)
        #pragma unroll
        for (int j = 0; j < 4; j++) acc[nt][j] = 0.0f;
    MMA_LOOP64T(acc, xs, g_wff2);

    float p_lo = 0.0f, p_hi = 0.0f;
    #pragma unroll
    for (int nt = 0; nt < 8; nt++) {
        int cc = nt * 8 + tig * 2;
        float b0 = b2fs[cc], b1 = b2fs[cc + 1];
        float w0 = w3s[cc],  w1 = w3s[cc + 1];
        p_lo = fmaf(lrelu(acc[nt][0] + b0), w0, p_lo);
        p_lo = fmaf(lrelu(acc[nt][1] + b1), w1, p_lo);
        p_hi = fmaf(lrelu(acc[nt][2] + b0), w0, p_hi);
        p_hi = fmaf(lrelu(acc[nt][3] + b1), w1, p_hi);
    }
    #pragma unroll
    for (int o = 1; o < 4; o <<= 1) {
        p_lo += __shfl_xor_sync(0xffffffffu, p_lo, o);
        p_hi += __shfl_xor_sync(0xffffffffu, p_hi, o);
    }
    int r_lo = row0 + wr + gid;
    int r_hi = r_lo + 8;
    if (tig == 0) {
        float bb = b3[0];
        if (r_lo < Bn) out[r_lo] = p_lo + bb;
        if (r_hi < Bn) out[r_hi] = p_hi + bb;
    }
}

// ---------------------------------------------------------------------------
extern "C" void kernel_launch(void* const* d_in, const int* in_sizes, int n_in,
                              void* d_out, int out_size) {
    const float* x    = (const float*)d_in[0];
    const int*   src  = (const int*)  d_in[1];
    const int*   dst  = (const int*)  d_in[2];
    const int*   bidx = (const int*)  d_in[3];
    const float* W1   = (const float*)d_in[4];
    const float* b1   = (const float*)d_in[5];
    const float* W2   = (const float*)d_in[6];
    const float* b2   = (const float*)d_in[7];
    const float* fc1w = (const float*)d_in[8];
    const float* fc1b = (const float*)d_in[9];
    const float* fc2w = (const float*)d_in[10];
    const float* fc2b = (const float*)d_in[11];
    const float* fc3w = (const float*)d_in[12];
    const float* fc3b = (const float*)d_in[13];
    const float* bn1g = (const float*)d_in[14];
    const float* bn1b = (const float*)d_in[15];
    const float* bn2g = (const float*)d_in[16];
    const float* bn2b = (const float*)d_in[17];

    int n  = in_sizes[0] / 128;   // nodes
    int E  = in_sizes[1];         // edges
    int Bn = in_sizes[3] / 2;     // pairs
    float* out = (float*)d_out;

    int eb  = (E + 255) / 256;
    int nb  = (n + 255) / 256;
    int nsb = (n + 1023) / 1024;
    int gb  = (n + 127) / 128;
    int gbB = (Bn + 127) / 128;

    // One-time host-side setup (first call is the uncaptured correctness run):
    // smem attribute + side stream / fork-join events. No device allocation.
    static cudaStream_t s2 = nullptr;
    static cudaEvent_t evFork = nullptr, evJoin = nullptr;
    if (!s2) {
        cudaFuncSetAttribute(k_gemm1, cudaFuncAttributeMaxDynamicSharedMemorySize, G1_SMEM);
        cudaStreamCreateWithFlags(&s2, cudaStreamNonBlocking);
        cudaEventCreateWithFlags(&evFork, cudaEventDisableTiming);
        cudaEventCreateWithFlags(&evJoin, cudaEventDisableTiming);
    }

    // Main stream: prep0 -> deg, then FORK:
    //   side stream s2: CSR build (scan1 -> scan3 -> fill)   [LTS/atomic-bound]
    //   main stream:    gemm1                                 [DRAM+tensor-bound]
    // JOIN before agg1 (needs g_h + CSR). Fork-join via events is the
    // documented graph-capture pattern; ordering also holds eagerly.
    k_prep0<<<512, 256>>>(W1, W2, fc1w, fc2w, n);
    k_deg  <<<eb, 256>>>(src, dst, E);

    cudaEventRecord(evFork, 0);
    cudaStreamWaitEvent(s2, evFork, 0);
    k_scan1<<<nsb, 256, 0, s2>>>(n);
    k_scan3<<<nb, 256, 0, s2>>>(n, nsb);
    k_fill <<<eb, 256, 0, s2>>>(src, dst, E);
    cudaEventRecord(evJoin, s2);

    k_gemm1<<<gb, 256, G1_SMEM>>>(x, n);      // concurrent with CSR build
    cudaStreamWaitEvent(0, evJoin, 0);

    // conv1 aggregation
    k_agg1 <<<1184, 256>>>(b1, n);

    // conv2 (bn1 + leaky fused into gemm2 load)
    k_gemm2f<<<gb, 256>>>(bn1g, bn1b, n, 1.0f / n);
    k_agg2  <<<1184, 256>>>(b2, n);

    // head
    k_fc1  <<<gbB, 256>>>(bidx, fc1b, Bn);
    k_final<<<gbB, 256>>>(fc2b, fc3w, fc3b, bn2g, bn2b, Bn, 1.0f / Bn, out);
}